// round 16
// baseline (speedup 1.0000x reference)
#include <cuda_runtime.h>
#include <cuda_bf16.h>
#include <cstdint>
#include <math.h>

#define NNODES 16384

// ═══════════ scratch: packed bf16 hi/lo planes (u32 = 2 k-consecutive bf16) ═══════════
__device__ uint32_t d_schi[(long)NNODES * 192], d_sclo[(long)NNODES * 192];
__device__ uint32_t d_hhi [(long)NNODES * 192], d_hlo [(long)NNODES * 192];
__device__ uint32_t d_ghi [(long)NNODES * 192], d_glo [(long)NNODES * 192];
__device__ uint32_t d_vthi[3L * NNODES * 128],  d_vtlo[3L * NNODES * 128];
__device__ uint32_t d_w1hi[2L * 384 * 192], d_w1lo[2L * 384 * 192];
__device__ uint32_t d_w2hi[2L * 640 * 192], d_w2lo[2L * 640 * 192];
__device__ uint32_t d_w0hi[2L * 128 * 192], d_w0lo[2L * 128 * 192];
__device__ uint32_t d_wvhi[2L * 128 * 128], d_wvlo[2L * 128 * 128];
__device__ float d_scf[(long)NNODES * 384];   // fp32 sc (for gating epilogue)
__device__ float d_s  [(long)NNODES * 128];   // scalar state fp32
__device__ float d_v  [(long)NNODES * 384];   // vector state fp32 (N, C, 3)

// ═══════════ helpers ═══════════
__device__ __forceinline__ uint32_t smem_u32(const void* p) {
    uint32_t a;
    asm("{ .reg .u64 t; cvta.to.shared.u64 t, %1; cvt.u32.u64 %0, t; }" : "=r"(a) : "l"(p));
    return a;
}
__device__ __forceinline__ void cp16(uint32_t dst, const void* src) {
    asm volatile("cp.async.cg.shared.global [%0], [%1], 16;" :: "r"(dst), "l"(src));
}
__device__ __forceinline__ void bsplit2(float e0, float e1, uint32_t& hi, uint32_t& lo) {
    __nv_bfloat162 hp = __floats2bfloat162_rn(e0, e1);
    uint32_t h = *reinterpret_cast<uint32_t*>(&hp);
    float h0 = __uint_as_float(h << 16);
    float h1 = __uint_as_float(h & 0xffff0000u);
    __nv_bfloat162 lp = __floats2bfloat162_rn(e0 - h0, e1 - h1);
    hi = h;
    lo = *reinterpret_cast<uint32_t*>(&lp);
}
__device__ __forceinline__ void mma16(float* c, const uint32_t* a, const uint32_t* b) {
    asm volatile(
        "mma.sync.aligned.m16n8k16.row.col.f32.bf16.bf16.f32 "
        "{%0,%1,%2,%3},{%4,%5,%6,%7},{%8,%9},{%0,%1,%2,%3};"
        : "+f"(c[0]), "+f"(c[1]), "+f"(c[2]), "+f"(c[3])
        : "r"(a[0]), "r"(a[1]), "r"(a[2]), "r"(a[3]), "r"(b[0]), "r"(b[1]));
}
__device__ __forceinline__ void ldm4(uint32_t* r, uint32_t addr) {
    asm volatile("ldmatrix.sync.aligned.m8n8.x4.shared.b16 {%0,%1,%2,%3}, [%4];"
        : "=r"(r[0]), "=r"(r[1]), "=r"(r[2]), "=r"(r[3]) : "r"(addr));
}

// ═══════════ weight pre-split: fp32 [K][N] -> bf16 hi/lo planes [N][K/2] u32 ═══════════
__global__ void wsplit_kernel(const float* __restrict__ w1, const float* __restrict__ w2,
                              const float* __restrict__ w0, const float* __restrict__ wv)
{
    const int z = blockIdx.y, wsel = z & 3, layer = z >> 2;
    const float* W; int ldw, K2, N; uint32_t *dhi, *dlo;
    if (wsel == 0) { W = w1 + (long)layer * 384 * 384; ldw = 384; K2 = 192; N = 384;
                     dhi = d_w1hi + (long)layer * 384 * 192; dlo = d_w1lo + (long)layer * 384 * 192; }
    else if (wsel == 1) { W = w2 + (long)layer * 384 * 768; ldw = 768; K2 = 192; N = 640;
                     dhi = d_w2hi + (long)layer * 640 * 192; dlo = d_w2lo + (long)layer * 640 * 192; }
    else if (wsel == 2) { W = w0 + (long)layer * 384 * 128; ldw = 128; K2 = 192; N = 128;
                     dhi = d_w0hi + (long)layer * 128 * 192; dlo = d_w0lo + (long)layer * 128 * 192; }
    else { W = wv + (long)layer * 256 * 128; ldw = 128; K2 = 128; N = 128;
                     dhi = d_wvhi + (long)layer * 128 * 128; dlo = d_wvlo + (long)layer * 128 * 128; }
    int idx = blockIdx.x * 256 + threadIdx.x;
    if (idx >= N * K2) return;
    int n = idx / K2, k2 = idx % K2;
    float f0 = W[(long)(2 * k2) * ldw + n];
    float f1 = W[(long)(2 * k2 + 1) * ldw + n];
    uint32_t hi, lo;
    bsplit2(f0, f1, hi, lo);
    dhi[(long)n * K2 + k2] = hi;
    dlo[(long)n * K2 + k2] = lo;
}

// ═══════════ prep: x -> sc planes + scf + state ═══════════
__global__ void prep_kernel(const float* __restrict__ x)
{
    int idx = blockIdx.x * blockDim.x + threadIdx.x;
    if (idx >= NNODES * 64) return;
    int n = idx >> 6, c2 = idx & 63, c0 = 2 * c2;
    float2 s2 = *(const float2*)&x[(long)n * 512 + c0];
    const float* xv = x + (long)n * 512 + 128 + 3 * c0;
    float2 a = *(const float2*)(xv), b = *(const float2*)(xv + 2), cc = *(const float2*)(xv + 4);
    float vv0 = (a.x * a.x + a.y * a.y + b.x * b.x) * 0.57735026918962576451f;
    float vv1 = (b.y * b.y + cc.x * cc.x + cc.y * cc.y) * 0.57735026918962576451f;
    float ss0 = s2.x * s2.x, ss1 = s2.y * s2.y;
    float* scf = d_scf + (long)n * 384;
    *(float2*)&scf[c0] = s2;
    *(float2*)&scf[128 + c0] = make_float2(ss0, ss1);
    *(float2*)&scf[256 + c0] = make_float2(vv0, vv1);
    uint32_t hi, lo;
    long pb = (long)n * 192 + c2;
    bsplit2(s2.x, s2.y, hi, lo);  d_schi[pb] = hi;       d_sclo[pb] = lo;
    bsplit2(ss0, ss1, hi, lo);    d_schi[pb + 64] = hi;  d_sclo[pb + 64] = lo;
    bsplit2(vv0, vv1, hi, lo);    d_schi[pb + 128] = hi; d_sclo[pb + 128] = lo;
    *(float2*)&d_s[(long)n * 128 + c0] = s2;
    float* vb = d_v + (long)n * 384 + 3 * c0;
    *(float2*)(vb) = a; *(float2*)(vb + 2) = b; *(float2*)(vb + 4) = cc;
}

// ═══════════ equivariant layernorm (64 thr/node) fused with next prep ═══════════
__device__ __forceinline__ float red64(float v, float* sh, int t)
{
    #pragma unroll
    for (int o = 16; o; o >>= 1) v += __shfl_xor_sync(0xffffffffu, v, o);
    if ((t & 31) == 0) sh[t >> 5] = v;
    __syncthreads();
    v = sh[0] + sh[1];
    __syncthreads();
    return v;
}

__global__ void ln_kernel(const float* __restrict__ g0, const float* __restrict__ g1)
{
    __shared__ float sh[2];
    int n = blockIdx.x, t = threadIdx.x, c0 = 2 * t;
    float s0 = d_s[(long)n * 128 + c0], s1 = d_s[(long)n * 128 + c0 + 1];
    float mu = red64(s0 + s1, sh, t) * (1.0f / 128.0f);
    float dd0 = s0 - mu, dd1 = s1 - mu;
    float var = red64(dd0 * dd0 + dd1 * dd1, sh, t) * (1.0f / 128.0f);
    float sd = sqrtf(var + 1e-6f);
    float* vp = d_v + (long)n * 384 + 3 * c0;
    float v0 = vp[0], v1 = vp[1], v2 = vp[2], v3 = vp[3], v4 = vp[4], v5 = vp[5];
    float msq = red64(v0*v0 + v1*v1 + v2*v2 + v3*v3 + v4*v4 + v5*v5, sh, t) * (1.0f / 384.0f);
    float rms = sqrtf(msq + 1e-6f);
    float sn0 = dd0 / sd * g0[c0], sn1 = dd1 / sd * g0[c0 + 1];
    d_s[(long)n * 128 + c0] = sn0; d_s[(long)n * 128 + c0 + 1] = sn1;
    float sc0 = g1[c0] / rms, sc1 = g1[c0 + 1] / rms;
    float nx0 = v0 * sc0, ny0 = v1 * sc0, nz0 = v2 * sc0;
    float nx1 = v3 * sc1, ny1 = v4 * sc1, nz1 = v5 * sc1;
    vp[0] = nx0; vp[1] = ny0; vp[2] = nz0; vp[3] = nx1; vp[4] = ny1; vp[5] = nz1;
    float vv0 = (nx0*nx0 + ny0*ny0 + nz0*nz0) * 0.57735026918962576451f;
    float vv1 = (nx1*nx1 + ny1*ny1 + nz1*nz1) * 0.57735026918962576451f;
    float* scf = d_scf + (long)n * 384;
    scf[c0] = sn0; scf[c0 + 1] = sn1;
    scf[128 + c0] = sn0 * sn0; scf[128 + c0 + 1] = sn1 * sn1;
    scf[256 + c0] = vv0; scf[256 + c0 + 1] = vv1;
    uint32_t hi, lo;
    long pb = (long)n * 192 + t;
    bsplit2(sn0, sn1, hi, lo);          d_schi[pb] = hi;       d_sclo[pb] = lo;
    bsplit2(sn0*sn0, sn1*sn1, hi, lo);  d_schi[pb + 64] = hi;  d_sclo[pb + 64] = lo;
    bsplit2(vv0, vv1, hi, lo);          d_schi[pb + 128] = hi; d_sclo[pb + 128] = lo;
}

// ═══════════ pure-bf16 mainloop: BK=16, ST=12 pad, 4-stage deep pipeline ═══════════
// Stage (u32): Ahi[128][12] | Alo | Bhi | Blo (8 data u32 + 4 pad per row) = 24KB.
// Conflict-free: granule index (3r+g) mod 8 is a bijection over any 8 consecutive rows.
static constexpr int ST = 12;
static constexpr int OFF_ALO = 128 * ST;
static constexpr int OFF_BHI = 2 * 128 * ST;
static constexpr int OFF_BLO = 3 * 128 * ST;
static constexpr int STAGE32 = 4 * 128 * ST;              // 6144 u32 = 24KB
static constexpr uint32_t SMEM_BYTES = 4 * STAGE32 * 4;   // 98304

__device__ __forceinline__ void bf16_loop(
    const uint32_t* __restrict__ Ahi, const uint32_t* __restrict__ Alo, int lda32,
    const uint32_t* __restrict__ Bhi, const uint32_t* __restrict__ Blo, int ldb32,
    int nch, uint32_t* sm, float (*cacc)[4],
    int t, int wm, int wn)
{
    const uint32_t smb = smem_u32(sm);
    const int lane = t & 31;
    const int la = lane & 15, ha = lane >> 4;                       // A frag lane map
    const int lb = lane & 7, tb = (lane >> 4) & 1, hb = (lane >> 3) & 1;  // B frag lane map
    const uint32_t aoff0 = (uint32_t)((wm + la) * ST + ha * 4);
    const uint32_t boff0 = (uint32_t)((wn + tb * 8 + lb) * ST + hb * 4);

    auto issue = [&](int ch) {
        const int kt = ch * 8;                        // 8 u32 = 16 bf16 k per chunk
        const uint32_t s0 = smb + (uint32_t)((ch & 3) * STAGE32) * 4u;
        const int r = t >> 1, c4 = (t & 1) * 4;       // 128 rows x 2 granules per plane
        const uint32_t off = (uint32_t)(r * ST + c4);
        cp16(s0 + off * 4u,             Ahi + (long)r * lda32 + kt + c4);
        cp16(s0 + (OFF_ALO + off) * 4u, Alo + (long)r * lda32 + kt + c4);
        cp16(s0 + (OFF_BHI + off) * 4u, Bhi + (long)r * ldb32 + kt + c4);
        cp16(s0 + (OFF_BLO + off) * 4u, Blo + (long)r * ldb32 + kt + c4);
        asm volatile("cp.async.commit_group;" ::: "memory");
    };

    issue(0); issue(1); issue(2);
    for (int ch = 0; ch < nch; ch++) {
        // exact wait so chunk ch is guaranteed landed even in the tail
        if (ch + 3 <= nch)      asm volatile("cp.async.wait_group 2;" ::: "memory");
        else if (ch + 2 <= nch) asm volatile("cp.async.wait_group 1;" ::: "memory");
        else                    asm volatile("cp.async.wait_group 0;" ::: "memory");
        __syncthreads();                               // visibility + frees stage (ch-1)&3
        if (ch + 3 < nch) issue(ch + 3);
        const uint32_t sbase = smb + (uint32_t)((ch & 3) * STAGE32) * 4u;

        uint32_t ah[4][4], al[4][4];
        #pragma unroll
        for (int mt = 0; mt < 4; mt++) {
            ldm4(ah[mt], sbase + (aoff0 + (uint32_t)(mt * 16 * ST)) * 4u);
            ldm4(al[mt], sbase + (OFF_ALO + aoff0 + (uint32_t)(mt * 16 * ST)) * 4u);
        }
        uint32_t bh[2][4], bl[2][4];   // pair p: r0,r1 = n-tile 2p ; r2,r3 = n-tile 2p+1
        #pragma unroll
        for (int p = 0; p < 2; p++) {
            ldm4(bh[p], sbase + (OFF_BHI + boff0 + (uint32_t)(p * 16 * ST)) * 4u);
            ldm4(bl[p], sbase + (OFF_BLO + boff0 + (uint32_t)(p * 16 * ST)) * 4u);
        }
        // pass-outer: 16 independent accumulators between reuses
        #pragma unroll
        for (int p = 0; p < 3; p++) {
            #pragma unroll
            for (int mt = 0; mt < 4; mt++) {
                const uint32_t* aa = (p == 1) ? al[mt] : ah[mt];
                #pragma unroll
                for (int nt = 0; nt < 4; nt++) {
                    const uint32_t* bb = (p == 2) ? &bl[nt >> 1][(nt & 1) * 2]
                                                  : &bh[nt >> 1][(nt & 1) * 2];
                    mma16(cacc[mt * 4 + nt], aa, bb);
                }
            }
        }
    }
}

#define GEMM_PROLOG \
    extern __shared__ uint32_t smu[]; \
    const int t = threadIdx.x, lane = t & 31, w = t >> 5; \
    const int g = lane >> 2, tig = lane & 3; \
    const int wm = (w & 1) * 64, wn = (w >> 1) * 32; \
    float cacc[16][4]; \
    _Pragma("unroll") \
    for (int i = 0; i < 16; i++) { cacc[i][0] = cacc[i][1] = cacc[i][2] = cacc[i][3] = 0.0f; }

#define EPI_LOOP(...) \
    _Pragma("unroll") \
    for (int mt = 0; mt < 4; mt++) \
        _Pragma("unroll") \
        for (int nt = 0; nt < 4; nt++) { \
            const float* cf = cacc[mt * 4 + nt]; \
            const int rb = row0 + wm + mt * 16 + g; \
            const int cc = col0 + wn + nt * 8 + 2 * tig; \
            _Pragma("unroll") \
            for (int hh = 0; hh < 2; hh++) { \
                const int row = rb + hh * 8; \
                float v0 = cf[hh * 2 + 0] * scale; \
                float v1 = cf[hh * 2 + 1] * scale; \
                __VA_ARGS__ \
            } \
        }

// GEMM1: h = silu(sc @ W1 / sqrt384) -> h planes
__global__ void __launch_bounds__(256, 2)
gemm1_kernel(const uint32_t* __restrict__ Bhi, const uint32_t* __restrict__ Blo, float scale)
{
    GEMM_PROLOG
    const int row0 = blockIdx.y * 128, col0 = blockIdx.x * 128;
    bf16_loop(d_schi + (long)row0 * 192, d_sclo + (long)row0 * 192, 192,
              Bhi + (long)col0 * 192, Blo + (long)col0 * 192, 192,
              24, smu, cacc, t, wm, wn);
    EPI_LOOP(
        v0 = v0 / (1.0f + expf(-v0));
        v1 = v1 / (1.0f + expf(-v1));
        uint32_t hi, lo;
        bsplit2(v0, v1, hi, lo);
        d_hhi[(long)row * 192 + (cc >> 1)] = hi;
        d_hlo[(long)row * 192 + (cc >> 1)] = lo;
    )
}

// GEMM2: g = h @ W2[:, :640] / sqrt384, fused gating -> g planes + vt planes
__global__ void __launch_bounds__(256, 2)
gemm2_kernel(const uint32_t* __restrict__ Bhi, const uint32_t* __restrict__ Blo, float scale)
{
    GEMM_PROLOG
    const int row0 = blockIdx.y * 128, col0 = blockIdx.x * 128;
    bf16_loop(d_hhi + (long)row0 * 192, d_hlo + (long)row0 * 192, 192,
              Bhi + (long)col0 * 192, Blo + (long)col0 * 192, 192,
              24, smu, cacc, t, wm, wn);
    EPI_LOOP(
        uint32_t hi, lo;
        if (col0 < 384) {
            const float2 ss = *(const float2*)&d_scf[(long)row * 384 + cc];
            bsplit2(v0 * ss.x, v1 * ss.y, hi, lo);
            d_ghi[(long)row * 192 + (cc >> 1)] = hi;
            d_glo[(long)row * 192 + (cc >> 1)] = lo;
        } else if (col0 == 384) {
            const int m = cc - 384;
            const float* vp = d_v + (long)row * 384 + 3 * m;
            #pragma unroll
            for (int d = 0; d < 3; d++) {
                bsplit2(vp[d] * v0, vp[3 + d] * v1, hi, lo);
                d_vthi[(long)d * NNODES * 128 + (long)row * 128 + (m >> 1)] = hi;
                d_vtlo[(long)d * NNODES * 128 + (long)row * 128 + (m >> 1)] = lo;
            }
        } else {
            const int m = cc - 512;
            const float a0 = 1.41421356237309514547f * d_scf[(long)row * 384 + m] * v0;
            const float a1 = 1.41421356237309514547f * d_scf[(long)row * 384 + m + 1] * v1;
            const float* vp = d_v + (long)row * 384 + 3 * m;
            #pragma unroll
            for (int d = 0; d < 3; d++) {
                bsplit2(vp[d] * a0, vp[3 + d] * a1, hi, lo);
                d_vthi[(long)d * NNODES * 128 + (long)row * 128 + 64 + (m >> 1)] = hi;
                d_vtlo[(long)d * NNODES * 128 + (long)row * 128 + 64 + (m >> 1)] = lo;
            }
        }
    )
}

// GEMM3 + vGEMM merged: z=0 scalar path, z=1..3 vector component d=z-1
__global__ void __launch_bounds__(256, 2)
gemmsv_kernel(const uint32_t* __restrict__ W0hi, const uint32_t* __restrict__ W0lo,
              const uint32_t* __restrict__ WVhi, const uint32_t* __restrict__ WVlo,
              float* __restrict__ Cs, int ldcs,
              float* __restrict__ Cv, int ldcv, int cvoff,
              float s384, float s256)
{
    GEMM_PROLOG
    const int row0 = blockIdx.y * 128, col0 = 0;
    const int z = blockIdx.z;
    if (z == 0) {
        const float scale = s384;
        bf16_loop(d_ghi + (long)row0 * 192, d_glo + (long)row0 * 192, 192,
                  W0hi, W0lo, 192, 24, smu, cacc, t, wm, wn);
        EPI_LOOP(
            const float2 rr = *(const float2*)&d_s[(long)row * 128 + cc];
            *(float2*)&Cs[(long)row * ldcs + cc] = make_float2(v0 + rr.x, v1 + rr.y);
        )
    } else {
        const float scale = s256;
        const int d = z - 1;
        bf16_loop(d_vthi + (long)d * NNODES * 128 + (long)row0 * 128,
                  d_vtlo + (long)d * NNODES * 128 + (long)row0 * 128, 128,
                  WVhi, WVlo, 128, 16, smu, cacc, t, wm, wn);
        EPI_LOOP(
            v0 += d_v[(long)row * 384 + 3 * cc + d];
            v1 += d_v[(long)row * 384 + 3 * (cc + 1) + d];
            Cv[(long)row * ldcv + cvoff + 3 * cc + d] = v0;
            Cv[(long)row * ldcv + cvoff + 3 * (cc + 1) + d] = v1;
        )
    }
}

// ═══════════ orchestration ═══════════
extern "C" void kernel_launch(void* const* d_in, const int* in_sizes, int n_in,
                              void* d_out, int out_size)
{
    const float* x  = (const float*)d_in[0];
    const float* w1 = (const float*)d_in[1];
    const float* w2 = (const float*)d_in[2];
    const float* w0 = (const float*)d_in[3];
    const float* wv = (const float*)d_in[4];
    const float* g0 = (const float*)d_in[5];
    const float* g1 = (const float*)d_in[6];
    float* out = (float*)d_out;

    uint32_t *w1hi, *w1lo, *w2hi, *w2lo, *w0hi, *w0lo, *wvhi, *wvlo;
    float *sb, *vb;
    cudaGetSymbolAddress((void**)&w1hi, d_w1hi); cudaGetSymbolAddress((void**)&w1lo, d_w1lo);
    cudaGetSymbolAddress((void**)&w2hi, d_w2hi); cudaGetSymbolAddress((void**)&w2lo, d_w2lo);
    cudaGetSymbolAddress((void**)&w0hi, d_w0hi); cudaGetSymbolAddress((void**)&w0lo, d_w0lo);
    cudaGetSymbolAddress((void**)&wvhi, d_wvhi); cudaGetSymbolAddress((void**)&wvlo, d_wvlo);
    cudaGetSymbolAddress((void**)&sb, d_s);
    cudaGetSymbolAddress((void**)&vb, d_v);

    cudaFuncSetAttribute((const void*)gemm1_kernel, cudaFuncAttributeMaxDynamicSharedMemorySize, SMEM_BYTES);
    cudaFuncSetAttribute((const void*)gemm2_kernel, cudaFuncAttributeMaxDynamicSharedMemorySize, SMEM_BYTES);
    cudaFuncSetAttribute((const void*)gemmsv_kernel, cudaFuncAttributeMaxDynamicSharedMemorySize, SMEM_BYTES);

    const float s384 = 1.0f / sqrtf(384.0f);
    const float s256 = 1.0f / 16.0f;

    dim3 thr(256);
    wsplit_kernel<<<dim3(480, 8), thr>>>(w1, w2, w0, wv);
    prep_kernel<<<(NNODES * 64) / 256, thr>>>(x);

    for (int layer = 0; layer < 2; layer++) {
        gemm1_kernel<<<dim3(3, 128), thr, SMEM_BYTES>>>(
            w1hi + (long)layer * 384 * 192, w1lo + (long)layer * 384 * 192, s384);
        gemm2_kernel<<<dim3(5, 128), thr, SMEM_BYTES>>>(
            w2hi + (long)layer * 640 * 192, w2lo + (long)layer * 640 * 192, s384);
        float* Cs = (layer == 0) ? sb : out;
        int ldcs = (layer == 0) ? 128 : 512;
        float* Cv = (layer == 0) ? vb : out;
        int ldcv = (layer == 0) ? 384 : 512;
        int cvoff = (layer == 0) ? 0 : 128;
        gemmsv_kernel<<<dim3(1, 128, 4), thr, SMEM_BYTES>>>(
            w0hi + (long)layer * 128 * 192, w0lo + (long)layer * 128 * 192,
            wvhi + (long)layer * 128 * 128, wvlo + (long)layer * 128 * 128,
            Cs, ldcs, Cv, ldcv, cvoff, s384, s256);
        if (layer == 0) ln_kernel<<<NNODES, 64>>>(g0, g1);
    }
}

// round 17
// speedup vs baseline: 1.2240x; 1.2240x over previous
#include <cuda_runtime.h>
#include <cuda_bf16.h>
#include <cstdint>
#include <math.h>

#define NNODES 16384

// ═══════════ scratch: packed bf16 hi/lo planes (u32 = 2 k-consecutive bf16) ═══════════
__device__ uint32_t d_schi[(long)NNODES * 192], d_sclo[(long)NNODES * 192];
__device__ uint32_t d_hhi [(long)NNODES * 192], d_hlo [(long)NNODES * 192];
__device__ uint32_t d_ghi [(long)NNODES * 192], d_glo [(long)NNODES * 192];
__device__ uint32_t d_vthi[3L * NNODES * 128],  d_vtlo[3L * NNODES * 128];
__device__ uint32_t d_w1hi[2L * 384 * 192], d_w1lo[2L * 384 * 192];
__device__ uint32_t d_w2hi[2L * 640 * 192], d_w2lo[2L * 640 * 192];
__device__ uint32_t d_w0hi[2L * 128 * 192], d_w0lo[2L * 128 * 192];
__device__ uint32_t d_wvhi[2L * 128 * 128], d_wvlo[2L * 128 * 128];
__device__ float d_scf[(long)NNODES * 384];   // fp32 sc (for gating epilogue)
__device__ float d_s  [(long)NNODES * 128];   // scalar state fp32
__device__ float d_v  [(long)NNODES * 384];   // vector state fp32 (N, C, 3)

// ═══════════ helpers ═══════════
__device__ __forceinline__ uint32_t smem_u32(const void* p) {
    uint32_t a;
    asm("{ .reg .u64 t; cvta.to.shared.u64 t, %1; cvt.u32.u64 %0, t; }" : "=r"(a) : "l"(p));
    return a;
}
__device__ __forceinline__ void cp16(uint32_t dst, const void* src) {
    asm volatile("cp.async.cg.shared.global [%0], [%1], 16;" :: "r"(dst), "l"(src));
}
__device__ __forceinline__ void cp16ca(uint32_t dst, const void* src) {
    asm volatile("cp.async.ca.shared.global [%0], [%1], 16;" :: "r"(dst), "l"(src));
}
__device__ __forceinline__ void bsplit2(float e0, float e1, uint32_t& hi, uint32_t& lo) {
    __nv_bfloat162 hp = __floats2bfloat162_rn(e0, e1);
    uint32_t h = *reinterpret_cast<uint32_t*>(&hp);
    float h0 = __uint_as_float(h << 16);
    float h1 = __uint_as_float(h & 0xffff0000u);
    __nv_bfloat162 lp = __floats2bfloat162_rn(e0 - h0, e1 - h1);
    hi = h;
    lo = *reinterpret_cast<uint32_t*>(&lp);
}
__device__ __forceinline__ void mma16(float* c, const uint32_t* a, const uint32_t* b) {
    asm volatile(
        "mma.sync.aligned.m16n8k16.row.col.f32.bf16.bf16.f32 "
        "{%0,%1,%2,%3},{%4,%5,%6,%7},{%8,%9},{%0,%1,%2,%3};"
        : "+f"(c[0]), "+f"(c[1]), "+f"(c[2]), "+f"(c[3])
        : "r"(a[0]), "r"(a[1]), "r"(a[2]), "r"(a[3]), "r"(b[0]), "r"(b[1]));
}
__device__ __forceinline__ void ldm4(uint32_t* r, uint32_t addr) {
    asm volatile("ldmatrix.sync.aligned.m8n8.x4.shared.b16 {%0,%1,%2,%3}, [%4];"
        : "=r"(r[0]), "=r"(r[1]), "=r"(r[2]), "=r"(r[3]) : "r"(addr));
}

// ═══════════ weight pre-split: fp32 [K][N] -> bf16 hi/lo planes [N][K/2] u32 ═══════════
__global__ void wsplit_kernel(const float* __restrict__ w1, const float* __restrict__ w2,
                              const float* __restrict__ w0, const float* __restrict__ wv)
{
    const int z = blockIdx.y, wsel = z & 3, layer = z >> 2;
    const float* W; int ldw, K2, N; uint32_t *dhi, *dlo;
    if (wsel == 0) { W = w1 + (long)layer * 384 * 384; ldw = 384; K2 = 192; N = 384;
                     dhi = d_w1hi + (long)layer * 384 * 192; dlo = d_w1lo + (long)layer * 384 * 192; }
    else if (wsel == 1) { W = w2 + (long)layer * 384 * 768; ldw = 768; K2 = 192; N = 640;
                     dhi = d_w2hi + (long)layer * 640 * 192; dlo = d_w2lo + (long)layer * 640 * 192; }
    else if (wsel == 2) { W = w0 + (long)layer * 384 * 128; ldw = 128; K2 = 192; N = 128;
                     dhi = d_w0hi + (long)layer * 128 * 192; dlo = d_w0lo + (long)layer * 128 * 192; }
    else { W = wv + (long)layer * 256 * 128; ldw = 128; K2 = 128; N = 128;
                     dhi = d_wvhi + (long)layer * 128 * 128; dlo = d_wvlo + (long)layer * 128 * 128; }
    int idx = blockIdx.x * 256 + threadIdx.x;
    if (idx >= N * K2) return;
    int n = idx / K2, k2 = idx % K2;
    float f0 = W[(long)(2 * k2) * ldw + n];
    float f1 = W[(long)(2 * k2 + 1) * ldw + n];
    uint32_t hi, lo;
    bsplit2(f0, f1, hi, lo);
    dhi[(long)n * K2 + k2] = hi;
    dlo[(long)n * K2 + k2] = lo;
}

// ═══════════ prep: x -> sc planes + scf + state ═══════════
__global__ void prep_kernel(const float* __restrict__ x)
{
    int idx = blockIdx.x * blockDim.x + threadIdx.x;
    if (idx >= NNODES * 64) return;
    int n = idx >> 6, c2 = idx & 63, c0 = 2 * c2;
    float2 s2 = *(const float2*)&x[(long)n * 512 + c0];
    const float* xv = x + (long)n * 512 + 128 + 3 * c0;
    float2 a = *(const float2*)(xv), b = *(const float2*)(xv + 2), cc = *(const float2*)(xv + 4);
    float vv0 = (a.x * a.x + a.y * a.y + b.x * b.x) * 0.57735026918962576451f;
    float vv1 = (b.y * b.y + cc.x * cc.x + cc.y * cc.y) * 0.57735026918962576451f;
    float ss0 = s2.x * s2.x, ss1 = s2.y * s2.y;
    float* scf = d_scf + (long)n * 384;
    *(float2*)&scf[c0] = s2;
    *(float2*)&scf[128 + c0] = make_float2(ss0, ss1);
    *(float2*)&scf[256 + c0] = make_float2(vv0, vv1);
    uint32_t hi, lo;
    long pb = (long)n * 192 + c2;
    bsplit2(s2.x, s2.y, hi, lo);  d_schi[pb] = hi;       d_sclo[pb] = lo;
    bsplit2(ss0, ss1, hi, lo);    d_schi[pb + 64] = hi;  d_sclo[pb + 64] = lo;
    bsplit2(vv0, vv1, hi, lo);    d_schi[pb + 128] = hi; d_sclo[pb + 128] = lo;
    *(float2*)&d_s[(long)n * 128 + c0] = s2;
    float* vb = d_v + (long)n * 384 + 3 * c0;
    *(float2*)(vb) = a; *(float2*)(vb + 2) = b; *(float2*)(vb + 4) = cc;
}

// ═══════════ equivariant layernorm (64 thr/node) fused with next prep ═══════════
__device__ __forceinline__ float red64(float v, float* sh, int t)
{
    #pragma unroll
    for (int o = 16; o; o >>= 1) v += __shfl_xor_sync(0xffffffffu, v, o);
    if ((t & 31) == 0) sh[t >> 5] = v;
    __syncthreads();
    v = sh[0] + sh[1];
    __syncthreads();
    return v;
}

__global__ void ln_kernel(const float* __restrict__ g0, const float* __restrict__ g1)
{
    __shared__ float sh[2];
    int n = blockIdx.x, t = threadIdx.x, c0 = 2 * t;
    float s0 = d_s[(long)n * 128 + c0], s1 = d_s[(long)n * 128 + c0 + 1];
    float mu = red64(s0 + s1, sh, t) * (1.0f / 128.0f);
    float dd0 = s0 - mu, dd1 = s1 - mu;
    float var = red64(dd0 * dd0 + dd1 * dd1, sh, t) * (1.0f / 128.0f);
    float sd = sqrtf(var + 1e-6f);
    float* vp = d_v + (long)n * 384 + 3 * c0;
    float v0 = vp[0], v1 = vp[1], v2 = vp[2], v3 = vp[3], v4 = vp[4], v5 = vp[5];
    float msq = red64(v0*v0 + v1*v1 + v2*v2 + v3*v3 + v4*v4 + v5*v5, sh, t) * (1.0f / 384.0f);
    float rms = sqrtf(msq + 1e-6f);
    float sn0 = dd0 / sd * g0[c0], sn1 = dd1 / sd * g0[c0 + 1];
    d_s[(long)n * 128 + c0] = sn0; d_s[(long)n * 128 + c0 + 1] = sn1;
    float sc0 = g1[c0] / rms, sc1 = g1[c0 + 1] / rms;
    float nx0 = v0 * sc0, ny0 = v1 * sc0, nz0 = v2 * sc0;
    float nx1 = v3 * sc1, ny1 = v4 * sc1, nz1 = v5 * sc1;
    vp[0] = nx0; vp[1] = ny0; vp[2] = nz0; vp[3] = nx1; vp[4] = ny1; vp[5] = nz1;
    float vv0 = (nx0*nx0 + ny0*ny0 + nz0*nz0) * 0.57735026918962576451f;
    float vv1 = (nx1*nx1 + ny1*ny1 + nz1*nz1) * 0.57735026918962576451f;
    float* scf = d_scf + (long)n * 384;
    scf[c0] = sn0; scf[c0 + 1] = sn1;
    scf[128 + c0] = sn0 * sn0; scf[128 + c0 + 1] = sn1 * sn1;
    scf[256 + c0] = vv0; scf[256 + c0 + 1] = vv1;
    uint32_t hi, lo;
    long pb = (long)n * 192 + t;
    bsplit2(sn0, sn1, hi, lo);          d_schi[pb] = hi;       d_sclo[pb] = lo;
    bsplit2(sn0*sn0, sn1*sn1, hi, lo);  d_schi[pb + 64] = hi;  d_sclo[pb + 64] = lo;
    bsplit2(vv0, vv1, hi, lo);          d_schi[pb + 128] = hi; d_sclo[pb + 128] = lo;
}

// ═══════════ pure-bf16 mainloop (R15 structure; B loads via .ca for L1 reuse) ═══════════
// SMEM per stage (u32): Ahi[128][20] | Alo | Bhi | Blo ; 16 data u32 + 4 pad per row.
static constexpr int ST = 20;
static constexpr int OFF_ALO = 128 * ST;
static constexpr int OFF_BHI = 2 * 128 * ST;
static constexpr int OFF_BLO = 3 * 128 * ST;
static constexpr int STAGE32 = 4 * 128 * ST;
static constexpr uint32_t SMEM_BYTES = 2 * STAGE32 * 4;   // 81920

__device__ __forceinline__ void bf16_loop(
    const uint32_t* __restrict__ Ahi, const uint32_t* __restrict__ Alo, int lda32,
    const uint32_t* __restrict__ Bhi, const uint32_t* __restrict__ Blo, int ldb32,
    int nch, uint32_t* sm, float (*cacc)[4],
    int t, int wm, int wn)
{
    const uint32_t smb = smem_u32(sm);
    const int lane = t & 31;
    // ldmatrix per-lane offsets (u32 units within a stage)
    const int la = lane & 15, ha = lane >> 4;                       // A: row within tile, k-half
    const int lb = lane & 7, tb = (lane >> 4) & 1, hb = (lane >> 3) & 1;  // B
    const uint32_t aoff0 = (uint32_t)((wm + la) * ST + ha * 4);
    const uint32_t boff0 = (uint32_t)((wn + tb * 8 + lb) * ST + hb * 4);

    {
        const uint32_t s0 = smb;
        #pragma unroll
        for (int i = 0; i < 2; i++) {
            int idx = t + i * 256;
            int r = idx >> 2, c4 = (idx & 3) * 4;
            cp16(s0 + (uint32_t)(r * ST + c4) * 4u,             Ahi + (long)r * lda32 + c4);
            cp16(s0 + (uint32_t)(OFF_ALO + r * ST + c4) * 4u,   Alo + (long)r * lda32 + c4);
            cp16ca(s0 + (uint32_t)(OFF_BHI + r * ST + c4) * 4u, Bhi + (long)r * ldb32 + c4);
            cp16ca(s0 + (uint32_t)(OFF_BLO + r * ST + c4) * 4u, Blo + (long)r * ldb32 + c4);
        }
        asm volatile("cp.async.commit_group;" ::: "memory");
    }
    for (int ch = 0; ch < nch; ch++) {
        const bool more = (ch + 1 < nch);
        if (more) {
            const int kt = (ch + 1) * 16;
            const uint32_t s0 = smb + (uint32_t)(((ch + 1) & 1) * STAGE32) * 4u;
            #pragma unroll
            for (int i = 0; i < 2; i++) {
                int idx = t + i * 256;
                int r = idx >> 2, c4 = (idx & 3) * 4;
                cp16(s0 + (uint32_t)(r * ST + c4) * 4u,             Ahi + (long)r * lda32 + kt + c4);
                cp16(s0 + (uint32_t)(OFF_ALO + r * ST + c4) * 4u,   Alo + (long)r * lda32 + kt + c4);
                cp16ca(s0 + (uint32_t)(OFF_BHI + r * ST + c4) * 4u, Bhi + (long)r * ldb32 + kt + c4);
                cp16ca(s0 + (uint32_t)(OFF_BLO + r * ST + c4) * 4u, Blo + (long)r * ldb32 + kt + c4);
            }
            asm volatile("cp.async.commit_group;" ::: "memory");
            asm volatile("cp.async.wait_group 1;" ::: "memory");
        } else {
            asm volatile("cp.async.wait_group 0;" ::: "memory");
        }
        __syncthreads();
        const uint32_t sbase = smb + (uint32_t)((ch & 1) * STAGE32) * 4u;
        #pragma unroll
        for (int ks = 0; ks < 2; ks++) {
            const uint32_t ko = (uint32_t)(ks * 8);
            uint32_t ah[4][4], al[4][4];
            #pragma unroll
            for (int mt = 0; mt < 4; mt++) {
                ldm4(ah[mt], sbase + (aoff0 + (uint32_t)(mt * 16 * ST) + ko) * 4u);
                ldm4(al[mt], sbase + (OFF_ALO + aoff0 + (uint32_t)(mt * 16 * ST) + ko) * 4u);
            }
            uint32_t bh[2][4], bl[2][4];   // pair p: r0,r1 = tile 2p ; r2,r3 = tile 2p+1
            #pragma unroll
            for (int p = 0; p < 2; p++) {
                ldm4(bh[p], sbase + (OFF_BHI + boff0 + (uint32_t)(p * 16 * ST) + ko) * 4u);
                ldm4(bl[p], sbase + (OFF_BLO + boff0 + (uint32_t)(p * 16 * ST) + ko) * 4u);
            }
            // pass-outer: 16 independent accumulators between reuses of any accumulator
            #pragma unroll
            for (int p = 0; p < 3; p++) {
                #pragma unroll
                for (int mt = 0; mt < 4; mt++) {
                    const uint32_t* aa = (p == 1) ? al[mt] : ah[mt];
                    #pragma unroll
                    for (int nt = 0; nt < 4; nt++) {
                        const uint32_t* bb = (p == 2) ? &bl[nt >> 1][(nt & 1) * 2]
                                                      : &bh[nt >> 1][(nt & 1) * 2];
                        mma16(cacc[mt * 4 + nt], aa, bb);
                    }
                }
            }
        }
        if (more) __syncthreads();   // release the buffer issue(ch+2) will write
    }
}

#define GEMM_PROLOG \
    extern __shared__ uint32_t smu[]; \
    const int t = threadIdx.x, lane = t & 31, w = t >> 5; \
    const int g = lane >> 2, tig = lane & 3; \
    const int wm = (w & 1) * 64, wn = (w >> 1) * 32; \
    float cacc[16][4]; \
    _Pragma("unroll") \
    for (int i = 0; i < 16; i++) { cacc[i][0] = cacc[i][1] = cacc[i][2] = cacc[i][3] = 0.0f; }

#define EPI_LOOP(...) \
    _Pragma("unroll") \
    for (int mt = 0; mt < 4; mt++) \
        _Pragma("unroll") \
        for (int nt = 0; nt < 4; nt++) { \
            const float* cf = cacc[mt * 4 + nt]; \
            const int rb = row0 + wm + mt * 16 + g; \
            const int cc = col0 + wn + nt * 8 + 2 * tig; \
            _Pragma("unroll") \
            for (int hh = 0; hh < 2; hh++) { \
                const int row = rb + hh * 8; \
                float v0 = cf[hh * 2 + 0] * scale; \
                float v1 = cf[hh * 2 + 1] * scale; \
                __VA_ARGS__ \
            } \
        }

// GEMM1: h = silu(sc @ W1 / sqrt384) -> h planes      [grid: x=row-tile, y=col-tile]
__global__ void __launch_bounds__(256, 2)
gemm1_kernel(const uint32_t* __restrict__ Bhi, const uint32_t* __restrict__ Blo, float scale)
{
    GEMM_PROLOG
    const int row0 = blockIdx.x * 128, col0 = blockIdx.y * 128;
    bf16_loop(d_schi + (long)row0 * 192, d_sclo + (long)row0 * 192, 192,
              Bhi + (long)col0 * 192, Blo + (long)col0 * 192, 192,
              12, smu, cacc, t, wm, wn);
    EPI_LOOP(
        v0 = v0 / (1.0f + expf(-v0));
        v1 = v1 / (1.0f + expf(-v1));
        uint32_t hi, lo;
        bsplit2(v0, v1, hi, lo);
        d_hhi[(long)row * 192 + (cc >> 1)] = hi;
        d_hlo[(long)row * 192 + (cc >> 1)] = lo;
    )
}

// GEMM2: g = h @ W2[:, :640] / sqrt384, fused gating   [grid: x=row-tile, y=col-tile]
__global__ void __launch_bounds__(256, 2)
gemm2_kernel(const uint32_t* __restrict__ Bhi, const uint32_t* __restrict__ Blo, float scale)
{
    GEMM_PROLOG
    const int row0 = blockIdx.x * 128, col0 = blockIdx.y * 128;
    bf16_loop(d_hhi + (long)row0 * 192, d_hlo + (long)row0 * 192, 192,
              Bhi + (long)col0 * 192, Blo + (long)col0 * 192, 192,
              12, smu, cacc, t, wm, wn);
    EPI_LOOP(
        uint32_t hi, lo;
        if (col0 < 384) {
            const float2 ss = *(const float2*)&d_scf[(long)row * 384 + cc];
            bsplit2(v0 * ss.x, v1 * ss.y, hi, lo);
            d_ghi[(long)row * 192 + (cc >> 1)] = hi;
            d_glo[(long)row * 192 + (cc >> 1)] = lo;
        } else if (col0 == 384) {
            const int m = cc - 384;
            const float* vp = d_v + (long)row * 384 + 3 * m;
            #pragma unroll
            for (int d = 0; d < 3; d++) {
                bsplit2(vp[d] * v0, vp[3 + d] * v1, hi, lo);
                d_vthi[(long)d * NNODES * 128 + (long)row * 128 + (m >> 1)] = hi;
                d_vtlo[(long)d * NNODES * 128 + (long)row * 128 + (m >> 1)] = lo;
            }
        } else {
            const int m = cc - 512;
            const float a0 = 1.41421356237309514547f * d_scf[(long)row * 384 + m] * v0;
            const float a1 = 1.41421356237309514547f * d_scf[(long)row * 384 + m + 1] * v1;
            const float* vp = d_v + (long)row * 384 + 3 * m;
            #pragma unroll
            for (int d = 0; d < 3; d++) {
                bsplit2(vp[d] * a0, vp[3 + d] * a1, hi, lo);
                d_vthi[(long)d * NNODES * 128 + (long)row * 128 + 64 + (m >> 1)] = hi;
                d_vtlo[(long)d * NNODES * 128 + (long)row * 128 + 64 + (m >> 1)] = lo;
            }
        }
    )
}

// GEMM3 + vGEMM merged: z=0 scalar path, z=1..3 vector component d=z-1
__global__ void __launch_bounds__(256, 2)
gemmsv_kernel(const uint32_t* __restrict__ W0hi, const uint32_t* __restrict__ W0lo,
              const uint32_t* __restrict__ WVhi, const uint32_t* __restrict__ WVlo,
              float* __restrict__ Cs, int ldcs,
              float* __restrict__ Cv, int ldcv, int cvoff,
              float s384, float s256)
{
    GEMM_PROLOG
    const int row0 = blockIdx.y * 128, col0 = 0;
    const int z = blockIdx.z;
    if (z == 0) {
        const float scale = s384;
        bf16_loop(d_ghi + (long)row0 * 192, d_glo + (long)row0 * 192, 192,
                  W0hi, W0lo, 192, 12, smu, cacc, t, wm, wn);
        EPI_LOOP(
            const float2 rr = *(const float2*)&d_s[(long)row * 128 + cc];
            *(float2*)&Cs[(long)row * ldcs + cc] = make_float2(v0 + rr.x, v1 + rr.y);
        )
    } else {
        const float scale = s256;
        const int d = z - 1;
        bf16_loop(d_vthi + (long)d * NNODES * 128 + (long)row0 * 128,
                  d_vtlo + (long)d * NNODES * 128 + (long)row0 * 128, 128,
                  WVhi, WVlo, 128, 8, smu, cacc, t, wm, wn);
        EPI_LOOP(
            v0 += d_v[(long)row * 384 + 3 * cc + d];
            v1 += d_v[(long)row * 384 + 3 * (cc + 1) + d];
            Cv[(long)row * ldcv + cvoff + 3 * cc + d] = v0;
            Cv[(long)row * ldcv + cvoff + 3 * (cc + 1) + d] = v1;
        )
    }
}

// ═══════════ orchestration ═══════════
extern "C" void kernel_launch(void* const* d_in, const int* in_sizes, int n_in,
                              void* d_out, int out_size)
{
    const float* x  = (const float*)d_in[0];
    const float* w1 = (const float*)d_in[1];
    const float* w2 = (const float*)d_in[2];
    const float* w0 = (const float*)d_in[3];
    const float* wv = (const float*)d_in[4];
    const float* g0 = (const float*)d_in[5];
    const float* g1 = (const float*)d_in[6];
    float* out = (float*)d_out;

    uint32_t *w1hi, *w1lo, *w2hi, *w2lo, *w0hi, *w0lo, *wvhi, *wvlo;
    float *sb, *vb;
    cudaGetSymbolAddress((void**)&w1hi, d_w1hi); cudaGetSymbolAddress((void**)&w1lo, d_w1lo);
    cudaGetSymbolAddress((void**)&w2hi, d_w2hi); cudaGetSymbolAddress((void**)&w2lo, d_w2lo);
    cudaGetSymbolAddress((void**)&w0hi, d_w0hi); cudaGetSymbolAddress((void**)&w0lo, d_w0lo);
    cudaGetSymbolAddress((void**)&wvhi, d_wvhi); cudaGetSymbolAddress((void**)&wvlo, d_wvlo);
    cudaGetSymbolAddress((void**)&sb, d_s);
    cudaGetSymbolAddress((void**)&vb, d_v);

    cudaFuncSetAttribute((const void*)gemm1_kernel, cudaFuncAttributeMaxDynamicSharedMemorySize, SMEM_BYTES);
    cudaFuncSetAttribute((const void*)gemm2_kernel, cudaFuncAttributeMaxDynamicSharedMemorySize, SMEM_BYTES);
    cudaFuncSetAttribute((const void*)gemmsv_kernel, cudaFuncAttributeMaxDynamicSharedMemorySize, SMEM_BYTES);

    const float s384 = 1.0f / sqrtf(384.0f);
    const float s256 = 1.0f / 16.0f;

    dim3 thr(256);
    wsplit_kernel<<<dim3(480, 8), thr>>>(w1, w2, w0, wv);
    prep_kernel<<<(NNODES * 64) / 256, thr>>>(x);

    for (int layer = 0; layer < 2; layer++) {
        // grid transposed: x=row-tile (fast), y=col-tile -> co-resident CTAs share B
        gemm1_kernel<<<dim3(128, 3), thr, SMEM_BYTES>>>(
            w1hi + (long)layer * 384 * 192, w1lo + (long)layer * 384 * 192, s384);
        gemm2_kernel<<<dim3(128, 5), thr, SMEM_BYTES>>>(
            w2hi + (long)layer * 640 * 192, w2lo + (long)layer * 640 * 192, s384);
        float* Cs = (layer == 0) ? sb : out;
        int ldcs = (layer == 0) ? 128 : 512;
        float* Cv = (layer == 0) ? vb : out;
        int ldcv = (layer == 0) ? 384 : 512;
        int cvoff = (layer == 0) ? 0 : 128;
        gemmsv_kernel<<<dim3(1, 128, 4), thr, SMEM_BYTES>>>(
            w0hi + (long)layer * 128 * 192, w0lo + (long)layer * 128 * 192,
            wvhi + (long)layer * 128 * 128, wvlo + (long)layer * 128 * 128,
            Cs, ldcs, Cv, ldcv, cvoff, s384, s256);
        if (layer == 0) ln_kernel<<<NNODES, 64>>>(g0, g1);
    }
}